// round 12
// baseline (speedup 1.0000x reference)
#include <cuda_runtime.h>
#include <cuda_fp16.h>
#include <math.h>
#include <stdint.h>

#define Nn 50000
#define Ee 800000
#define KIN 128
#define HCn 256
#define NHEAD 4
#define OC 64
#define NEG_SLOPE 0.2f

// ---------------- scratch (static device globals; no allocation) -------------
__device__ __align__(16) __half g_h[(size_t)Nn * HCn];   // 25.6 MB, fp16 features
__device__ float g_as[Nn * NHEAD];
__device__ float g_ad[Nn * NHEAD];
__device__ int   g_count[Nn];
__device__ int   g_cursor[Nn];
__device__ int   g_off[Nn + 1];
__device__ int   g_csr[Ee + Nn];
__device__ int   g_is64;

#define SB 1024
#define NSB ((Nn + SB - 1) / SB)            // 49
__device__ int   g_bsum[NSB];
__device__ int   g_bpre[NSB];

__device__ __forceinline__ uint32_t smem_to_u32(const void* smem_ptr) {
    uint32_t addr;
    asm("{ .reg .u64 tmp; cvta.to.shared.u64 tmp, %1; cvt.u32.u64 %0, tmp; }"
        : "=r"(addr) : "l"(smem_ptr));
    return addr;
}

// ---------------- edge index dtype detection ---------------------------------
__global__ void detect_kernel(const long long* __restrict__ ei) {
    if (threadIdx.x == 0) {
        int ok = 1;
        for (int i = 0; i < 8; i++) {
            long long v = ei[i];
            if (v < 0 || v >= Nn) ok = 0;
        }
        g_is64 = ok;
    }
}

__global__ void init_count_kernel() {
    int i = blockIdx.x * blockDim.x + threadIdx.x;
    if (i < Nn) g_count[i] = 1;             // self loop pre-counted
}

// histogram of dst straight from edge_index (no src/dst staging round-trip)
__global__ void count_kernel(const void* __restrict__ ei) {
    int i = blockIdx.x * blockDim.x + threadIdx.x;
    if (i >= Ee) return;
    int d;
    if (g_is64) {
        d = (int)((const long long*)ei)[Ee + i];
    } else {
        d = ((const int*)ei)[Ee + i];
    }
    atomicAdd(&g_count[d], 1);
}

// ---------------- 3-phase multi-block exclusive scan -------------------------
__global__ void __launch_bounds__(SB) scan_block_kernel() {
    __shared__ int sh[SB];
    int i = blockIdx.x * SB + threadIdx.x;
    int v = (i < Nn) ? g_count[i] : 0;
    sh[threadIdx.x] = v;
    __syncthreads();
    #pragma unroll
    for (int o = 1; o < SB; o <<= 1) {
        int t = (threadIdx.x >= o) ? sh[threadIdx.x - o] : 0;
        __syncthreads();
        sh[threadIdx.x] += t;
        __syncthreads();
    }
    if (i < Nn) g_off[i] = sh[threadIdx.x] - v;
    if (threadIdx.x == SB - 1) g_bsum[blockIdx.x] = sh[SB - 1];
}

__global__ void scan_spine_kernel() {
    __shared__ int sh[64];
    int t = threadIdx.x;
    int v = (t < NSB) ? g_bsum[t] : 0;
    sh[t] = v;
    __syncthreads();
    #pragma unroll
    for (int o = 1; o < 64; o <<= 1) {
        int x = (t >= o) ? sh[t - o] : 0;
        __syncthreads();
        sh[t] += x;
        __syncthreads();
    }
    if (t < NSB) g_bpre[t] = sh[t] - v;
    if (t == 63) g_off[Nn] = sh[63];
}

__global__ void scan_apply_kernel() {
    int i = blockIdx.x * blockDim.x + threadIdx.x;
    if (i < Nn) {
        int o = g_off[i] + g_bpre[i >> 10];
        g_off[i] = o;
        g_cursor[i] = o;
    }
}

// fill straight from edge_index
__global__ void fill_kernel(const void* __restrict__ ei) {
    int i = blockIdx.x * blockDim.x + threadIdx.x;
    if (i < Ee) {
        int s, d;
        if (g_is64) {
            const long long* p = (const long long*)ei;
            s = (int)p[i];
            d = (int)p[Ee + i];
        } else {
            const int* p = (const int*)ei;
            s = p[i];
            d = p[Ee + i];
        }
        int pos = atomicAdd(&g_cursor[d], 1);
        g_csr[pos] = s;
    } else if (i < Ee + Nn) {
        int n = i - Ee;
        int pos = atomicAdd(&g_cursor[n], 1);
        g_csr[pos] = n;                      // self loop
    }
}

// ================= GEMM: h = x @ W via HMMA, single-term fp16 ================
#define ASTR 272                    // 128 fp16 = 256B + 16B pad (cf ldmatrix)
#define GS_A 0
#define GS_B (128 * ASTR)           // 34816
#define GEMM_SMEM (2 * 128 * ASTR)  // 69632 B -> 2 CTA/SM

__device__ __forceinline__ void ldmx4(uint32_t* r, uint32_t addr) {
    asm volatile("ldmatrix.sync.aligned.m8n8.x4.shared.b16 {%0,%1,%2,%3}, [%4];"
                 : "=r"(r[0]), "=r"(r[1]), "=r"(r[2]), "=r"(r[3]) : "r"(addr));
}
__device__ __forceinline__ void ldmx4t(uint32_t& r0, uint32_t& r1, uint32_t& r2,
                                       uint32_t& r3, uint32_t addr) {
    asm volatile("ldmatrix.sync.aligned.m8n8.x4.trans.shared.b16 {%0,%1,%2,%3}, [%4];"
                 : "=r"(r0), "=r"(r1), "=r"(r2), "=r"(r3) : "r"(addr));
}
__device__ __forceinline__ void mma16816(float* c, const uint32_t* a, const uint32_t* b) {
    asm volatile("mma.sync.aligned.m16n8k16.row.col.f32.f16.f16.f32 "
                 "{%0,%1,%2,%3}, {%4,%5,%6,%7}, {%8,%9}, {%0,%1,%2,%3};"
                 : "+f"(c[0]), "+f"(c[1]), "+f"(c[2]), "+f"(c[3])
                 : "r"(a[0]), "r"(a[1]), "r"(a[2]), "r"(a[3]), "r"(b[0]), "r"(b[1]));
}

__device__ __forceinline__ uint32_t pack_h2(float a, float b) {
    __half2 h = __floats2half2_rn(a, b);
    return *(uint32_t*)&h;
}

__global__ void __launch_bounds__(256, 2) gemm_mma_kernel(const float* __restrict__ x,
                                                          const float* __restrict__ W,
                                                          const float* __restrict__ att_src,
                                                          const float* __restrict__ att_dst) {
    extern __shared__ char smem[];
    uint32_t sb = smem_to_u32(smem);
    int tid = threadIdx.x, wid = tid >> 5, lane = tid & 31;
    int m_blk = blockIdx.y * 128;
    int n_blk = blockIdx.x * 128;

    #pragma unroll
    for (int i = 0; i < 16; i++) {
        int idx = tid + i * 256;
        int r = idx >> 5;
        int kq = (idx & 31) * 4;
        int grow = m_blk + r;
        float4 v = (grow < Nn) ? *(const float4*)(x + (size_t)grow * KIN + kq)
                               : make_float4(0.f, 0.f, 0.f, 0.f);
        *(uint2*)(smem + GS_A + (uint32_t)r * ASTR + kq * 2) =
            make_uint2(pack_h2(v.x, v.y), pack_h2(v.z, v.w));
    }
    #pragma unroll
    for (int i = 0; i < 16; i++) {
        int idx = tid + i * 256;
        int k = idx >> 5;
        int nq = (idx & 31) * 4;
        float4 v = *(const float4*)(W + (size_t)k * HCn + n_blk + nq);
        *(uint2*)(smem + GS_B + (uint32_t)k * ASTR + nq * 2) =
            make_uint2(pack_h2(v.x, v.y), pack_h2(v.z, v.w));
    }
    __syncthreads();

    int m0 = (wid & 3) * 32;
    int n0 = (wid >> 2) * 64;
    float c[2][8][4] = {};

    int a_r16 = (lane & 7) + ((lane >> 3) & 1) * 8;
    int a_k8  = (lane >> 4) * 8;
    int b_mi  = lane >> 3;
    int b_k8  = (lane & 7) + (b_mi & 1) * 8;
    int b_n8  = (b_mi >> 1) * 8;

    #pragma unroll
    for (int k0 = 0; k0 < KIN; k0 += 16) {
        uint32_t a[2][4];
        #pragma unroll
        for (int mt = 0; mt < 2; mt++) {
            uint32_t addr = sb + GS_A + (uint32_t)(m0 + mt * 16 + a_r16) * ASTR
                          + (uint32_t)(k0 + a_k8) * 2;
            ldmx4(a[mt], addr);
        }
        uint32_t b[8][2];
        #pragma unroll
        for (int q = 0; q < 4; q++) {
            uint32_t addr = sb + GS_B + (uint32_t)(k0 + b_k8) * ASTR
                          + (uint32_t)(n0 + q * 16 + b_n8) * 2;
            uint32_t r0, r1, r2, r3;
            ldmx4t(r0, r1, r2, r3, addr);
            b[q * 2][0] = r0;     b[q * 2][1] = r1;
            b[q * 2 + 1][0] = r2; b[q * 2 + 1][1] = r3;
        }
        #pragma unroll
        for (int mt = 0; mt < 2; mt++)
            #pragma unroll
            for (int nt = 0; nt < 8; nt++)
                mma16816(c[mt][nt], a[mt], b[nt]);
    }

    // epilogue 1: store h as fp16
    int gr0 = m_blk + m0 + (lane >> 2);
    int gc0 = n_blk + n0 + (lane & 3) * 2;
    #pragma unroll
    for (int mt = 0; mt < 2; mt++) {
        #pragma unroll
        for (int nt = 0; nt < 8; nt++) {
            int row = gr0 + mt * 16;
            int col = gc0 + nt * 8;
            if (row < Nn)
                *(__half2*)(g_h + (size_t)row * HCn + col) =
                    __floats2half2_rn(c[mt][nt][0], c[mt][nt][1]);
            if (row + 8 < Nn)
                *(__half2*)(g_h + (size_t)(row + 8) * HCn + col) =
                    __floats2half2_rn(c[mt][nt][2], c[mt][nt][3]);
        }
    }

    // epilogue 2: fused attention halves. This warp's 64 cols == one head.
    {
        int head = (n_blk + n0) >> 6;
        const float* ws = att_src + head * OC;
        const float* wd = att_dst + head * OC;
        float asv[4] = {0.f, 0.f, 0.f, 0.f};
        float adv[4] = {0.f, 0.f, 0.f, 0.f};
        int cbase = (lane & 3) * 2;
        #pragma unroll
        for (int nt = 0; nt < 8; nt++) {
            float2 s2 = *(const float2*)(ws + nt * 8 + cbase);
            float2 d2 = *(const float2*)(wd + nt * 8 + cbase);
            #pragma unroll
            for (int sl = 0; sl < 4; sl++) {
                float c0 = c[sl >> 1][nt][(sl & 1) * 2];
                float c1 = c[sl >> 1][nt][(sl & 1) * 2 + 1];
                asv[sl] += c0 * s2.x + c1 * s2.y;
                adv[sl] += c0 * d2.x + c1 * d2.y;
            }
        }
        #pragma unroll
        for (int o = 1; o < 4; o <<= 1) {
            #pragma unroll
            for (int sl = 0; sl < 4; sl++) {
                asv[sl] += __shfl_xor_sync(0xffffffffu, asv[sl], o);
                adv[sl] += __shfl_xor_sync(0xffffffffu, adv[sl], o);
            }
        }
        if ((lane & 3) == 0) {
            int rbase = m_blk + m0 + (lane >> 2);
            #pragma unroll
            for (int sl = 0; sl < 4; sl++) {
                int row = rbase + ((sl >> 1) * 16) + ((sl & 1) * 8);
                if (row < Nn) {
                    g_as[row * NHEAD + head] = asv[sl];
                    g_ad[row * NHEAD + head] = adv[sl];
                }
            }
        }
    }
}

// ------- SINGLE-PASS agg: unnormalized exp-weighted gather, divide at end ----
__device__ __forceinline__ float lrelu(float e) {
    return e > 0.f ? e : NEG_SLOPE * e;
}

__global__ void __launch_bounds__(256) agg_kernel(const float* __restrict__ bias,
                                                  const float* __restrict__ gamma,
                                                  const float* __restrict__ beta,
                                                  float* __restrict__ out) {
    int wid = threadIdx.x >> 5, lane = threadIdx.x & 31;
    int n = blockIdx.x * 8 + wid;
    if (n >= Nn) return;
    int start = g_off[n], end = g_off[n + 1];
    int head = lane >> 3;                     // lane owns 8 contiguous channels
    float adh = g_ad[n * NHEAD + head];

    float acc[8] = {0.f, 0.f, 0.f, 0.f, 0.f, 0.f, 0.f, 0.f};
    float sw = 0.f;
    int e = start;
    for (; e + 4 <= end; e += 4) {            // unroll x4: 4 independent chains
        int s0 = g_csr[e + 0];
        int s1 = g_csr[e + 1];
        int s2 = g_csr[e + 2];
        int s3 = g_csr[e + 3];
        float w0 = __expf(lrelu(g_as[s0 * NHEAD + head] + adh));
        float w1 = __expf(lrelu(g_as[s1 * NHEAD + head] + adh));
        float w2 = __expf(lrelu(g_as[s2 * NHEAD + head] + adh));
        float w3 = __expf(lrelu(g_as[s3 * NHEAD + head] + adh));
        uint4 hv0 = *((const uint4*)(g_h + (size_t)s0 * HCn) + lane);
        uint4 hv1 = *((const uint4*)(g_h + (size_t)s1 * HCn) + lane);
        uint4 hv2 = *((const uint4*)(g_h + (size_t)s2 * HCn) + lane);
        uint4 hv3 = *((const uint4*)(g_h + (size_t)s3 * HCn) + lane);
        sw += (w0 + w1) + (w2 + w3);
        const __half2* a2 = (const __half2*)&hv0;
        const __half2* b2 = (const __half2*)&hv1;
        const __half2* c2 = (const __half2*)&hv2;
        const __half2* d2 = (const __half2*)&hv3;
        #pragma unroll
        for (int j = 0; j < 4; j++) {
            float2 fa = __half22float2(a2[j]);
            float2 fb = __half22float2(b2[j]);
            float2 fc = __half22float2(c2[j]);
            float2 fd = __half22float2(d2[j]);
            acc[j * 2]     += fa.x * w0 + fb.x * w1 + fc.x * w2 + fd.x * w3;
            acc[j * 2 + 1] += fa.y * w0 + fb.y * w1 + fc.y * w2 + fd.y * w3;
        }
    }
    for (; e < end; e++) {
        int s0 = g_csr[e];
        float w0 = __expf(lrelu(g_as[s0 * NHEAD + head] + adh));
        uint4 hv0 = *((const uint4*)(g_h + (size_t)s0 * HCn) + lane);
        sw += w0;
        const __half2* a2 = (const __half2*)&hv0;
        #pragma unroll
        for (int j = 0; j < 4; j++) {
            float2 fa = __half22float2(a2[j]);
            acc[j * 2]     += fa.x * w0;
            acc[j * 2 + 1] += fa.y * w0;
        }
    }

    float inv = 1.f / sw;

    float4 b0 = *(const float4*)(bias + lane * 8);
    float4 b1 = *(const float4*)(bias + lane * 8 + 4);
    float bb[8] = {b0.x, b0.y, b0.z, b0.w, b1.x, b1.y, b1.z, b1.w};
    #pragma unroll
    for (int j = 0; j < 8; j++) acc[j] = acc[j] * inv + bb[j];

    float s1 = 0.f, s2 = 0.f;
    #pragma unroll
    for (int j = 0; j < 8; j++) { s1 += acc[j]; s2 += acc[j] * acc[j]; }
    #pragma unroll
    for (int o = 16; o; o >>= 1) {
        s1 += __shfl_xor_sync(0xffffffffu, s1, o);
        s2 += __shfl_xor_sync(0xffffffffu, s2, o);
    }
    float mu = s1 * (1.f / HCn);
    float var = s2 * (1.f / HCn) - mu * mu;
    float rstd = rsqrtf(var + 1e-5f);

    float4 g0 = *(const float4*)(gamma + lane * 8);
    float4 g1 = *(const float4*)(gamma + lane * 8 + 4);
    float4 t0 = *(const float4*)(beta + lane * 8);
    float4 t1 = *(const float4*)(beta + lane * 8 + 4);
    float gm[8] = {g0.x, g0.y, g0.z, g0.w, g1.x, g1.y, g1.z, g1.w};
    float bt[8] = {t0.x, t0.y, t0.z, t0.w, t1.x, t1.y, t1.z, t1.w};

    float o8[8];
    #pragma unroll
    for (int j = 0; j < 8; j++) {
        float nm = (acc[j] - mu) * rstd * gm[j] + bt[j];
        o8[j] = nm > 0.f ? nm : expm1f(nm);
    }
    float* op = out + (size_t)n * HCn + lane * 8;
    *(float4*)op       = make_float4(o8[0], o8[1], o8[2], o8[3]);
    *(float4*)(op + 4) = make_float4(o8[4], o8[5], o8[6], o8[7]);
}

// ---------------- launch ------------------------------------------------------
extern "C" void kernel_launch(void* const* d_in, const int* in_sizes, int n_in,
                              void* d_out, int out_size) {
    const float* x       = (const float*)d_in[0];
    const void*  ei      = d_in[1];
    const float* W       = (const float*)d_in[2];
    const float* att_src = (const float*)d_in[3];
    const float* att_dst = (const float*)d_in[4];
    const float* bias    = (const float*)d_in[5];
    const float* gamma   = (const float*)d_in[6];
    const float* beta    = (const float*)d_in[7];
    float* out = (float*)d_out;

    static cudaStream_t sB = nullptr;
    static cudaEvent_t eFork = nullptr, eJoin = nullptr;
    static bool streams_ok = false;
    if (!sB) {
        streams_ok =
            (cudaStreamCreateWithFlags(&sB, cudaStreamNonBlocking) == cudaSuccess) &&
            (cudaEventCreateWithFlags(&eFork, cudaEventDisableTiming) == cudaSuccess) &&
            (cudaEventCreateWithFlags(&eJoin, cudaEventDisableTiming) == cudaSuccess);
    }
    cudaFuncSetAttribute(gemm_mma_kernel, cudaFuncAttributeMaxDynamicSharedMemorySize,
                         GEMM_SMEM);

    cudaStream_t csr = streams_ok ? sB : (cudaStream_t)0;
    if (streams_ok) {
        cudaEventRecord(eFork, 0);
        cudaStreamWaitEvent(sB, eFork, 0);
    }

    // CSR chain (incl. dtype detect) entirely on side stream
    detect_kernel<<<1, 32, 0, csr>>>((const long long*)ei);
    init_count_kernel<<<(Nn + 255) / 256, 256, 0, csr>>>();
    count_kernel<<<(Ee + 255) / 256, 256, 0, csr>>>(ei);
    scan_block_kernel<<<NSB, SB, 0, csr>>>();
    scan_spine_kernel<<<1, 64, 0, csr>>>();
    scan_apply_kernel<<<(Nn + 255) / 256, 256, 0, csr>>>();
    fill_kernel<<<(Ee + Nn + 255) / 256, 256, 0, csr>>>(ei);
    if (streams_ok) cudaEventRecord(eJoin, sB);

    // GEMM immediately on main stream — no dependency on edge_index
    gemm_mma_kernel<<<dim3(2, (Nn + 127) / 128), 256, GEMM_SMEM>>>(x, W, att_src, att_dst);

    if (streams_ok) cudaStreamWaitEvent((cudaStream_t)0, eJoin, 0);
    agg_kernel<<<(Nn + 7) / 8, 256>>>(bias, gamma, beta, out);
}

// round 13
// speedup vs baseline: 1.0319x; 1.0319x over previous
#include <cuda_runtime.h>
#include <cuda_fp16.h>
#include <math.h>
#include <stdint.h>

#define Nn 50000
#define Ee 800000
#define KIN 128
#define HCn 256
#define NHEAD 4
#define OC 64
#define NEG_SLOPE 0.2f

// ---------------- scratch (static device globals; no allocation) -------------
__device__ __align__(16) __half g_h[(size_t)Nn * HCn];   // 25.6 MB, fp16 features
__device__ float g_as[Nn * NHEAD];
__device__ float g_ad[Nn * NHEAD];
__device__ int   g_src[Ee];
__device__ int   g_dst[Ee];
__device__ int   g_count[Nn];
__device__ int   g_cursor[Nn];
__device__ int   g_off[Nn + 1];
__device__ int   g_csr[Ee + Nn];
__device__ int   g_is64;

#define SB 1024
#define NSB ((Nn + SB - 1) / SB)            // 49
__device__ int   g_bsum[NSB];

__device__ __forceinline__ uint32_t smem_to_u32(const void* smem_ptr) {
    uint32_t addr;
    asm("{ .reg .u64 tmp; cvta.to.shared.u64 tmp, %1; cvt.u32.u64 %0, tmp; }"
        : "=r"(addr) : "l"(smem_ptr));
    return addr;
}

// ---------------- edge index dtype detection ---------------------------------
__global__ void detect_kernel(const long long* __restrict__ ei) {
    if (threadIdx.x == 0) {
        int ok = 1;
        for (int i = 0; i < 8; i++) {
            long long v = ei[i];
            if (v < 0 || v >= Nn) ok = 0;
        }
        g_is64 = ok;
    }
}

__global__ void init_count_kernel() {
    int i = blockIdx.x * blockDim.x + threadIdx.x;
    if (i < Nn) g_count[i] = 1;             // self loop pre-counted
}

// convert + histogram in ONE pass over the edge list (staged int32 src/dst)
__global__ void convert_count_kernel(const void* __restrict__ ei) {
    int i = blockIdx.x * blockDim.x + threadIdx.x;
    if (i >= Ee) return;
    int s, d;
    if (g_is64) {
        const long long* p = (const long long*)ei;
        s = (int)p[i];
        d = (int)p[Ee + i];
    } else {
        const int* p = (const int*)ei;
        s = p[i];
        d = p[Ee + i];
    }
    g_src[i] = s;
    g_dst[i] = d;
    atomicAdd(&g_count[d], 1);
}

// ---------------- scan phase 1: per-block local exclusive scan ---------------
__global__ void __launch_bounds__(SB) scan_block_kernel() {
    __shared__ int sh[SB];
    int i = blockIdx.x * SB + threadIdx.x;
    int v = (i < Nn) ? g_count[i] : 0;
    sh[threadIdx.x] = v;
    __syncthreads();
    #pragma unroll
    for (int o = 1; o < SB; o <<= 1) {
        int t = (threadIdx.x >= o) ? sh[threadIdx.x - o] : 0;
        __syncthreads();
        sh[threadIdx.x] += t;
        __syncthreads();
    }
    if (i < Nn) g_off[i] = sh[threadIdx.x] - v;          // local exclusive
    if (threadIdx.x == SB - 1) g_bsum[blockIdx.x] = sh[SB - 1];
}

// ---------------- scan phase 2 (merged spine+apply) ---------------------------
// Each block redundantly computes the 49-element spine prefix (cheap), then
// applies it. Also writes the self-loop entry directly (slot off[n]) and
// starts cursors at off[n]+1, so fill needs NO self-loop atomics.
__global__ void __launch_bounds__(SB) scan_apply_kernel() {
    __shared__ int pre_sh;
    __shared__ int tot_sh;
    if (threadIdx.x == 0) {
        int pre = 0, tot = 0;
        #pragma unroll
        for (int b = 0; b < NSB; b++) {
            int v = g_bsum[b];
            if (b < (int)blockIdx.x) pre += v;
            tot += v;
        }
        pre_sh = pre;
        tot_sh = tot;
    }
    __syncthreads();
    int i = blockIdx.x * SB + threadIdx.x;
    if (i < Nn) {
        int o = g_off[i] + pre_sh;
        g_off[i] = o;
        g_cursor[i] = o + 1;                 // slot o reserved for self loop
        g_csr[o] = i;                        // self loop
    }
    if (blockIdx.x == NSB - 1 && threadIdx.x == SB - 1) g_off[Nn] = tot_sh;
}

__global__ void fill_kernel() {
    int i = blockIdx.x * blockDim.x + threadIdx.x;
    if (i < Ee) {
        int d = g_dst[i];
        int pos = atomicAdd(&g_cursor[d], 1);
        g_csr[pos] = g_src[i];
    }
}

// ================= GEMM: h = x @ W via HMMA, single-term fp16 ================
#define ASTR 272                    // 128 fp16 = 256B + 16B pad (cf ldmatrix)
#define GS_A 0
#define GS_B (128 * ASTR)           // 34816
#define GEMM_SMEM (2 * 128 * ASTR)  // 69632 B -> 2 CTA/SM

__device__ __forceinline__ void ldmx4(uint32_t* r, uint32_t addr) {
    asm volatile("ldmatrix.sync.aligned.m8n8.x4.shared.b16 {%0,%1,%2,%3}, [%4];"
                 : "=r"(r[0]), "=r"(r[1]), "=r"(r[2]), "=r"(r[3]) : "r"(addr));
}
__device__ __forceinline__ void ldmx4t(uint32_t& r0, uint32_t& r1, uint32_t& r2,
                                       uint32_t& r3, uint32_t addr) {
    asm volatile("ldmatrix.sync.aligned.m8n8.x4.trans.shared.b16 {%0,%1,%2,%3}, [%4];"
                 : "=r"(r0), "=r"(r1), "=r"(r2), "=r"(r3) : "r"(addr));
}
__device__ __forceinline__ void mma16816(float* c, const uint32_t* a, const uint32_t* b) {
    asm volatile("mma.sync.aligned.m16n8k16.row.col.f32.f16.f16.f32 "
                 "{%0,%1,%2,%3}, {%4,%5,%6,%7}, {%8,%9}, {%0,%1,%2,%3};"
                 : "+f"(c[0]), "+f"(c[1]), "+f"(c[2]), "+f"(c[3])
                 : "r"(a[0]), "r"(a[1]), "r"(a[2]), "r"(a[3]), "r"(b[0]), "r"(b[1]));
}

__device__ __forceinline__ uint32_t pack_h2(float a, float b) {
    __half2 h = __floats2half2_rn(a, b);
    return *(uint32_t*)&h;
}

__global__ void __launch_bounds__(256, 2) gemm_mma_kernel(const float* __restrict__ x,
                                                          const float* __restrict__ W,
                                                          const float* __restrict__ att_src,
                                                          const float* __restrict__ att_dst) {
    extern __shared__ char smem[];
    uint32_t sb = smem_to_u32(smem);
    int tid = threadIdx.x, wid = tid >> 5, lane = tid & 31;
    int m_blk = blockIdx.y * 128;
    int n_blk = blockIdx.x * 128;

    #pragma unroll
    for (int i = 0; i < 16; i++) {
        int idx = tid + i * 256;
        int r = idx >> 5;
        int kq = (idx & 31) * 4;
        int grow = m_blk + r;
        float4 v = (grow < Nn) ? *(const float4*)(x + (size_t)grow * KIN + kq)
                               : make_float4(0.f, 0.f, 0.f, 0.f);
        *(uint2*)(smem + GS_A + (uint32_t)r * ASTR + kq * 2) =
            make_uint2(pack_h2(v.x, v.y), pack_h2(v.z, v.w));
    }
    #pragma unroll
    for (int i = 0; i < 16; i++) {
        int idx = tid + i * 256;
        int k = idx >> 5;
        int nq = (idx & 31) * 4;
        float4 v = *(const float4*)(W + (size_t)k * HCn + n_blk + nq);
        *(uint2*)(smem + GS_B + (uint32_t)k * ASTR + nq * 2) =
            make_uint2(pack_h2(v.x, v.y), pack_h2(v.z, v.w));
    }
    __syncthreads();

    int m0 = (wid & 3) * 32;
    int n0 = (wid >> 2) * 64;
    float c[2][8][4] = {};

    int a_r16 = (lane & 7) + ((lane >> 3) & 1) * 8;
    int a_k8  = (lane >> 4) * 8;
    int b_mi  = lane >> 3;
    int b_k8  = (lane & 7) + (b_mi & 1) * 8;
    int b_n8  = (b_mi >> 1) * 8;

    #pragma unroll
    for (int k0 = 0; k0 < KIN; k0 += 16) {
        uint32_t a[2][4];
        #pragma unroll
        for (int mt = 0; mt < 2; mt++) {
            uint32_t addr = sb + GS_A + (uint32_t)(m0 + mt * 16 + a_r16) * ASTR
                          + (uint32_t)(k0 + a_k8) * 2;
            ldmx4(a[mt], addr);
        }
        uint32_t b[8][2];
        #pragma unroll
        for (int q = 0; q < 4; q++) {
            uint32_t addr = sb + GS_B + (uint32_t)(k0 + b_k8) * ASTR
                          + (uint32_t)(n0 + q * 16 + b_n8) * 2;
            uint32_t r0, r1, r2, r3;
            ldmx4t(r0, r1, r2, r3, addr);
            b[q * 2][0] = r0;     b[q * 2][1] = r1;
            b[q * 2 + 1][0] = r2; b[q * 2 + 1][1] = r3;
        }
        #pragma unroll
        for (int mt = 0; mt < 2; mt++)
            #pragma unroll
            for (int nt = 0; nt < 8; nt++)
                mma16816(c[mt][nt], a[mt], b[nt]);
    }

    // epilogue 1: store h as fp16
    int gr0 = m_blk + m0 + (lane >> 2);
    int gc0 = n_blk + n0 + (lane & 3) * 2;
    #pragma unroll
    for (int mt = 0; mt < 2; mt++) {
        #pragma unroll
        for (int nt = 0; nt < 8; nt++) {
            int row = gr0 + mt * 16;
            int col = gc0 + nt * 8;
            if (row < Nn)
                *(__half2*)(g_h + (size_t)row * HCn + col) =
                    __floats2half2_rn(c[mt][nt][0], c[mt][nt][1]);
            if (row + 8 < Nn)
                *(__half2*)(g_h + (size_t)(row + 8) * HCn + col) =
                    __floats2half2_rn(c[mt][nt][2], c[mt][nt][3]);
        }
    }

    // epilogue 2: fused attention halves. This warp's 64 cols == one head.
    {
        int head = (n_blk + n0) >> 6;
        const float* ws = att_src + head * OC;
        const float* wd = att_dst + head * OC;
        float asv[4] = {0.f, 0.f, 0.f, 0.f};
        float adv[4] = {0.f, 0.f, 0.f, 0.f};
        int cbase = (lane & 3) * 2;
        #pragma unroll
        for (int nt = 0; nt < 8; nt++) {
            float2 s2 = *(const float2*)(ws + nt * 8 + cbase);
            float2 d2 = *(const float2*)(wd + nt * 8 + cbase);
            #pragma unroll
            for (int sl = 0; sl < 4; sl++) {
                float c0 = c[sl >> 1][nt][(sl & 1) * 2];
                float c1 = c[sl >> 1][nt][(sl & 1) * 2 + 1];
                asv[sl] += c0 * s2.x + c1 * s2.y;
                adv[sl] += c0 * d2.x + c1 * d2.y;
            }
        }
        #pragma unroll
        for (int o = 1; o < 4; o <<= 1) {
            #pragma unroll
            for (int sl = 0; sl < 4; sl++) {
                asv[sl] += __shfl_xor_sync(0xffffffffu, asv[sl], o);
                adv[sl] += __shfl_xor_sync(0xffffffffu, adv[sl], o);
            }
        }
        if ((lane & 3) == 0) {
            int rbase = m_blk + m0 + (lane >> 2);
            #pragma unroll
            for (int sl = 0; sl < 4; sl++) {
                int row = rbase + ((sl >> 1) * 16) + ((sl & 1) * 8);
                if (row < Nn) {
                    g_as[row * NHEAD + head] = asv[sl];
                    g_ad[row * NHEAD + head] = adv[sl];
                }
            }
        }
    }
}

// ------- SINGLE-PASS agg: unnormalized exp-weighted gather, divide at end ----
__device__ __forceinline__ float lrelu(float e) {
    return e > 0.f ? e : NEG_SLOPE * e;
}

__global__ void __launch_bounds__(256) agg_kernel(const float* __restrict__ bias,
                                                  const float* __restrict__ gamma,
                                                  const float* __restrict__ beta,
                                                  float* __restrict__ out) {
    int wid = threadIdx.x >> 5, lane = threadIdx.x & 31;
    int n = blockIdx.x * 8 + wid;
    if (n >= Nn) return;
    int start = g_off[n], end = g_off[n + 1];
    int head = lane >> 3;                     // lane owns 8 contiguous channels
    float adh = g_ad[n * NHEAD + head];

    float acc[8] = {0.f, 0.f, 0.f, 0.f, 0.f, 0.f, 0.f, 0.f};
    float sw = 0.f;
    int e = start;
    for (; e + 4 <= end; e += 4) {            // unroll x4: 4 independent chains
        int s0 = g_csr[e + 0];
        int s1 = g_csr[e + 1];
        int s2 = g_csr[e + 2];
        int s3 = g_csr[e + 3];
        float w0 = __expf(lrelu(g_as[s0 * NHEAD + head] + adh));
        float w1 = __expf(lrelu(g_as[s1 * NHEAD + head] + adh));
        float w2 = __expf(lrelu(g_as[s2 * NHEAD + head] + adh));
        float w3 = __expf(lrelu(g_as[s3 * NHEAD + head] + adh));
        uint4 hv0 = *((const uint4*)(g_h + (size_t)s0 * HCn) + lane);
        uint4 hv1 = *((const uint4*)(g_h + (size_t)s1 * HCn) + lane);
        uint4 hv2 = *((const uint4*)(g_h + (size_t)s2 * HCn) + lane);
        uint4 hv3 = *((const uint4*)(g_h + (size_t)s3 * HCn) + lane);
        sw += (w0 + w1) + (w2 + w3);
        const __half2* a2 = (const __half2*)&hv0;
        const __half2* b2 = (const __half2*)&hv1;
        const __half2* c2 = (const __half2*)&hv2;
        const __half2* d2 = (const __half2*)&hv3;
        #pragma unroll
        for (int j = 0; j < 4; j++) {
            float2 fa = __half22float2(a2[j]);
            float2 fb = __half22float2(b2[j]);
            float2 fc = __half22float2(c2[j]);
            float2 fd = __half22float2(d2[j]);
            acc[j * 2]     += fa.x * w0 + fb.x * w1 + fc.x * w2 + fd.x * w3;
            acc[j * 2 + 1] += fa.y * w0 + fb.y * w1 + fc.y * w2 + fd.y * w3;
        }
    }
    for (; e < end; e++) {
        int s0 = g_csr[e];
        float w0 = __expf(lrelu(g_as[s0 * NHEAD + head] + adh));
        uint4 hv0 = *((const uint4*)(g_h + (size_t)s0 * HCn) + lane);
        sw += w0;
        const __half2* a2 = (const __half2*)&hv0;
        #pragma unroll
        for (int j = 0; j < 4; j++) {
            float2 fa = __half22float2(a2[j]);
            acc[j * 2]     += fa.x * w0;
            acc[j * 2 + 1] += fa.y * w0;
        }
    }

    float inv = 1.f / sw;

    float4 b0 = *(const float4*)(bias + lane * 8);
    float4 b1 = *(const float4*)(bias + lane * 8 + 4);
    float bb[8] = {b0.x, b0.y, b0.z, b0.w, b1.x, b1.y, b1.z, b1.w};
    #pragma unroll
    for (int j = 0; j < 8; j++) acc[j] = acc[j] * inv + bb[j];

    float s1 = 0.f, s2 = 0.f;
    #pragma unroll
    for (int j = 0; j < 8; j++) { s1 += acc[j]; s2 += acc[j] * acc[j]; }
    #pragma unroll
    for (int o = 16; o; o >>= 1) {
        s1 += __shfl_xor_sync(0xffffffffu, s1, o);
        s2 += __shfl_xor_sync(0xffffffffu, s2, o);
    }
    float mu = s1 * (1.f / HCn);
    float var = s2 * (1.f / HCn) - mu * mu;
    float rstd = rsqrtf(var + 1e-5f);

    float4 g0 = *(const float4*)(gamma + lane * 8);
    float4 g1 = *(const float4*)(gamma + lane * 8 + 4);
    float4 t0 = *(const float4*)(beta + lane * 8);
    float4 t1 = *(const float4*)(beta + lane * 8 + 4);
    float gm[8] = {g0.x, g0.y, g0.z, g0.w, g1.x, g1.y, g1.z, g1.w};
    float bt[8] = {t0.x, t0.y, t0.z, t0.w, t1.x, t1.y, t1.z, t1.w};

    float o8[8];
    #pragma unroll
    for (int j = 0; j < 8; j++) {
        float nm = (acc[j] - mu) * rstd * gm[j] + bt[j];
        o8[j] = nm > 0.f ? nm : expm1f(nm);
    }
    float* op = out + (size_t)n * HCn + lane * 8;
    *(float4*)op       = make_float4(o8[0], o8[1], o8[2], o8[3]);
    *(float4*)(op + 4) = make_float4(o8[4], o8[5], o8[6], o8[7]);
}

// ---------------- launch ------------------------------------------------------
extern "C" void kernel_launch(void* const* d_in, const int* in_sizes, int n_in,
                              void* d_out, int out_size) {
    const float* x       = (const float*)d_in[0];
    const void*  ei      = d_in[1];
    const float* W       = (const float*)d_in[2];
    const float* att_src = (const float*)d_in[3];
    const float* att_dst = (const float*)d_in[4];
    const float* bias    = (const float*)d_in[5];
    const float* gamma   = (const float*)d_in[6];
    const float* beta    = (const float*)d_in[7];
    float* out = (float*)d_out;

    static cudaStream_t sB = nullptr;
    static cudaEvent_t eFork = nullptr, eJoin = nullptr;
    static bool streams_ok = false;
    if (!sB) {
        streams_ok =
            (cudaStreamCreateWithFlags(&sB, cudaStreamNonBlocking) == cudaSuccess) &&
            (cudaEventCreateWithFlags(&eFork, cudaEventDisableTiming) == cudaSuccess) &&
            (cudaEventCreateWithFlags(&eJoin, cudaEventDisableTiming) == cudaSuccess);
    }
    cudaFuncSetAttribute(gemm_mma_kernel, cudaFuncAttributeMaxDynamicSharedMemorySize,
                         GEMM_SMEM);

    detect_kernel<<<1, 32>>>((const long long*)ei);

    cudaStream_t csr = streams_ok ? sB : (cudaStream_t)0;
    if (streams_ok) {
        cudaEventRecord(eFork, 0);
        cudaStreamWaitEvent(sB, eFork, 0);
    }

    // CSR-build chain on side stream (R11 structure + merged spine/apply)
    init_count_kernel<<<(Nn + 255) / 256, 256, 0, csr>>>();
    convert_count_kernel<<<(Ee + 255) / 256, 256, 0, csr>>>(ei);
    scan_block_kernel<<<NSB, SB, 0, csr>>>();
    scan_apply_kernel<<<NSB, SB, 0, csr>>>();
    fill_kernel<<<(Ee + 255) / 256, 256, 0, csr>>>();
    if (streams_ok) cudaEventRecord(eJoin, sB);

    // GEMM on main stream
    gemm_mma_kernel<<<dim3(2, (Nn + 127) / 128), 256, GEMM_SMEM>>>(x, W, att_src, att_dst);

    if (streams_ok) cudaStreamWaitEvent((cudaStream_t)0, eJoin, 0);
    agg_kernel<<<(Nn + 7) / 8, 256>>>(bias, gamma, beta, out);
}

// round 14
// speedup vs baseline: 1.0431x; 1.0109x over previous
#include <cuda_runtime.h>
#include <cuda_fp16.h>
#include <math.h>
#include <stdint.h>

#define Nn 50000
#define Ee 800000
#define KIN 128
#define HCn 256
#define NHEAD 4
#define OC 64
#define NEG_SLOPE 0.2f

// ---------------- scratch (static device globals; no allocation) -------------
__device__ __align__(16) __half g_h[(size_t)Nn * HCn];   // 25.6 MB, fp16 features
__device__ float g_as[Nn * NHEAD];
__device__ float g_ad[Nn * NHEAD];
__device__ int   g_src[Ee];
__device__ int   g_dst[Ee];
__device__ int   g_count[Nn];
__device__ int   g_cursor[Nn];
__device__ int   g_off[Nn + 1];
__device__ int   g_csr[Ee + Nn];
__device__ int   g_is64;

#define SB 1024
#define NSB ((Nn + SB - 1) / SB)            // 49
__device__ int   g_bsum[NSB];

__device__ __forceinline__ uint32_t smem_to_u32(const void* smem_ptr) {
    uint32_t addr;
    asm("{ .reg .u64 tmp; cvta.to.shared.u64 tmp, %1; cvt.u32.u64 %0, tmp; }"
        : "=r"(addr) : "l"(smem_ptr));
    return addr;
}

// ---------------- edge index dtype detection ---------------------------------
__global__ void detect_kernel(const long long* __restrict__ ei) {
    if (threadIdx.x == 0) {
        int ok = 1;
        for (int i = 0; i < 8; i++) {
            long long v = ei[i];
            if (v < 0 || v >= Nn) ok = 0;
        }
        g_is64 = ok;
    }
}

__global__ void init_count_kernel() {
    int i = blockIdx.x * blockDim.x + threadIdx.x;
    if (i < Nn) g_count[i] = 1;             // self loop pre-counted
}

// convert + histogram in ONE pass over the edge list (staged int32 src/dst)
__global__ void convert_count_kernel(const void* __restrict__ ei) {
    int i = blockIdx.x * blockDim.x + threadIdx.x;
    if (i >= Ee) return;
    int s, d;
    if (g_is64) {
        const long long* p = (const long long*)ei;
        s = (int)p[i];
        d = (int)p[Ee + i];
    } else {
        const int* p = (const int*)ei;
        s = p[i];
        d = p[Ee + i];
    }
    g_src[i] = s;
    g_dst[i] = d;
    atomicAdd(&g_count[d], 1);
}

// ---------------- scan phase 1: per-block local exclusive scan ---------------
__global__ void __launch_bounds__(SB) scan_block_kernel() {
    __shared__ int sh[SB];
    int i = blockIdx.x * SB + threadIdx.x;
    int v = (i < Nn) ? g_count[i] : 0;
    sh[threadIdx.x] = v;
    __syncthreads();
    #pragma unroll
    for (int o = 1; o < SB; o <<= 1) {
        int t = (threadIdx.x >= o) ? sh[threadIdx.x - o] : 0;
        __syncthreads();
        sh[threadIdx.x] += t;
        __syncthreads();
    }
    if (i < Nn) g_off[i] = sh[threadIdx.x] - v;          // local exclusive
    if (threadIdx.x == SB - 1) g_bsum[blockIdx.x] = sh[SB - 1];
}

// ---------------- scan phase 2 (merged spine+apply) ---------------------------
// Each block redundantly computes the 49-element spine prefix (cheap), then
// applies it. Also writes the self-loop entry directly (slot off[n]) and
// starts cursors at off[n]+1, so fill needs NO self-loop atomics.
__global__ void __launch_bounds__(SB) scan_apply_kernel() {
    __shared__ int pre_sh;
    __shared__ int tot_sh;
    if (threadIdx.x == 0) {
        int pre = 0, tot = 0;
        #pragma unroll
        for (int b = 0; b < NSB; b++) {
            int v = g_bsum[b];
            if (b < (int)blockIdx.x) pre += v;
            tot += v;
        }
        pre_sh = pre;
        tot_sh = tot;
    }
    __syncthreads();
    int i = blockIdx.x * SB + threadIdx.x;
    if (i < Nn) {
        int o = g_off[i] + pre_sh;
        g_off[i] = o;
        g_cursor[i] = o + 1;                 // slot o reserved for self loop
        g_csr[o] = i;                        // self loop
    }
    if (blockIdx.x == NSB - 1 && threadIdx.x == SB - 1) g_off[Nn] = tot_sh;
}

__global__ void fill_kernel() {
    int i = blockIdx.x * blockDim.x + threadIdx.x;
    if (i < Ee) {
        int d = g_dst[i];
        int pos = atomicAdd(&g_cursor[d], 1);
        g_csr[pos] = g_src[i];
    }
}

// ================= GEMM: h = x @ W via HMMA, single-term fp16 ================
#define ASTR 272                    // 128 fp16 = 256B + 16B pad (cf ldmatrix)
#define GS_A 0
#define GS_B (128 * ASTR)           // 34816
#define GEMM_SMEM (2 * 128 * ASTR)  // 69632 B -> 2 CTA/SM

__device__ __forceinline__ void ldmx4(uint32_t* r, uint32_t addr) {
    asm volatile("ldmatrix.sync.aligned.m8n8.x4.shared.b16 {%0,%1,%2,%3}, [%4];"
                 : "=r"(r[0]), "=r"(r[1]), "=r"(r[2]), "=r"(r[3]) : "r"(addr));
}
__device__ __forceinline__ void ldmx4t(uint32_t& r0, uint32_t& r1, uint32_t& r2,
                                       uint32_t& r3, uint32_t addr) {
    asm volatile("ldmatrix.sync.aligned.m8n8.x4.trans.shared.b16 {%0,%1,%2,%3}, [%4];"
                 : "=r"(r0), "=r"(r1), "=r"(r2), "=r"(r3) : "r"(addr));
}
__device__ __forceinline__ void mma16816(float* c, const uint32_t* a, const uint32_t* b) {
    asm volatile("mma.sync.aligned.m16n8k16.row.col.f32.f16.f16.f32 "
                 "{%0,%1,%2,%3}, {%4,%5,%6,%7}, {%8,%9}, {%0,%1,%2,%3};"
                 : "+f"(c[0]), "+f"(c[1]), "+f"(c[2]), "+f"(c[3])
                 : "r"(a[0]), "r"(a[1]), "r"(a[2]), "r"(a[3]), "r"(b[0]), "r"(b[1]));
}

__device__ __forceinline__ uint32_t pack_h2(float a, float b) {
    __half2 h = __floats2half2_rn(a, b);
    return *(uint32_t*)&h;
}

__global__ void __launch_bounds__(256, 2) gemm_mma_kernel(const float* __restrict__ x,
                                                          const float* __restrict__ W,
                                                          const float* __restrict__ att_src,
                                                          const float* __restrict__ att_dst) {
    extern __shared__ char smem[];
    uint32_t sb = smem_to_u32(smem);
    int tid = threadIdx.x, wid = tid >> 5, lane = tid & 31;
    int m_blk = blockIdx.y * 128;
    int n_blk = blockIdx.x * 128;

    #pragma unroll
    for (int i = 0; i < 16; i++) {
        int idx = tid + i * 256;
        int r = idx >> 5;
        int kq = (idx & 31) * 4;
        int grow = m_blk + r;
        float4 v = (grow < Nn) ? *(const float4*)(x + (size_t)grow * KIN + kq)
                               : make_float4(0.f, 0.f, 0.f, 0.f);
        *(uint2*)(smem + GS_A + (uint32_t)r * ASTR + kq * 2) =
            make_uint2(pack_h2(v.x, v.y), pack_h2(v.z, v.w));
    }
    #pragma unroll
    for (int i = 0; i < 16; i++) {
        int idx = tid + i * 256;
        int k = idx >> 5;
        int nq = (idx & 31) * 4;
        float4 v = *(const float4*)(W + (size_t)k * HCn + n_blk + nq);
        *(uint2*)(smem + GS_B + (uint32_t)k * ASTR + nq * 2) =
            make_uint2(pack_h2(v.x, v.y), pack_h2(v.z, v.w));
    }
    __syncthreads();

    int m0 = (wid & 3) * 32;
    int n0 = (wid >> 2) * 64;
    float c[2][8][4] = {};

    int a_r16 = (lane & 7) + ((lane >> 3) & 1) * 8;
    int a_k8  = (lane >> 4) * 8;
    int b_mi  = lane >> 3;
    int b_k8  = (lane & 7) + (b_mi & 1) * 8;
    int b_n8  = (b_mi >> 1) * 8;

    #pragma unroll
    for (int k0 = 0; k0 < KIN; k0 += 16) {
        uint32_t a[2][4];
        #pragma unroll
        for (int mt = 0; mt < 2; mt++) {
            uint32_t addr = sb + GS_A + (uint32_t)(m0 + mt * 16 + a_r16) * ASTR
                          + (uint32_t)(k0 + a_k8) * 2;
            ldmx4(a[mt], addr);
        }
        uint32_t b[8][2];
        #pragma unroll
        for (int q = 0; q < 4; q++) {
            uint32_t addr = sb + GS_B + (uint32_t)(k0 + b_k8) * ASTR
                          + (uint32_t)(n0 + q * 16 + b_n8) * 2;
            uint32_t r0, r1, r2, r3;
            ldmx4t(r0, r1, r2, r3, addr);
            b[q * 2][0] = r0;     b[q * 2][1] = r1;
            b[q * 2 + 1][0] = r2; b[q * 2 + 1][1] = r3;
        }
        #pragma unroll
        for (int mt = 0; mt < 2; mt++)
            #pragma unroll
            for (int nt = 0; nt < 8; nt++)
                mma16816(c[mt][nt], a[mt], b[nt]);
    }

    // epilogue 1: store h as fp16
    int gr0 = m_blk + m0 + (lane >> 2);
    int gc0 = n_blk + n0 + (lane & 3) * 2;
    #pragma unroll
    for (int mt = 0; mt < 2; mt++) {
        #pragma unroll
        for (int nt = 0; nt < 8; nt++) {
            int row = gr0 + mt * 16;
            int col = gc0 + nt * 8;
            if (row < Nn)
                *(__half2*)(g_h + (size_t)row * HCn + col) =
                    __floats2half2_rn(c[mt][nt][0], c[mt][nt][1]);
            if (row + 8 < Nn)
                *(__half2*)(g_h + (size_t)(row + 8) * HCn + col) =
                    __floats2half2_rn(c[mt][nt][2], c[mt][nt][3]);
        }
    }

    // epilogue 2: fused attention halves. This warp's 64 cols == one head.
    {
        int head = (n_blk + n0) >> 6;
        const float* ws = att_src + head * OC;
        const float* wd = att_dst + head * OC;
        float asv[4] = {0.f, 0.f, 0.f, 0.f};
        float adv[4] = {0.f, 0.f, 0.f, 0.f};
        int cbase = (lane & 3) * 2;
        #pragma unroll
        for (int nt = 0; nt < 8; nt++) {
            float2 s2 = *(const float2*)(ws + nt * 8 + cbase);
            float2 d2 = *(const float2*)(wd + nt * 8 + cbase);
            #pragma unroll
            for (int sl = 0; sl < 4; sl++) {
                float c0 = c[sl >> 1][nt][(sl & 1) * 2];
                float c1 = c[sl >> 1][nt][(sl & 1) * 2 + 1];
                asv[sl] += c0 * s2.x + c1 * s2.y;
                adv[sl] += c0 * d2.x + c1 * d2.y;
            }
        }
        #pragma unroll
        for (int o = 1; o < 4; o <<= 1) {
            #pragma unroll
            for (int sl = 0; sl < 4; sl++) {
                asv[sl] += __shfl_xor_sync(0xffffffffu, asv[sl], o);
                adv[sl] += __shfl_xor_sync(0xffffffffu, adv[sl], o);
            }
        }
        if ((lane & 3) == 0) {
            int rbase = m_blk + m0 + (lane >> 2);
            #pragma unroll
            for (int sl = 0; sl < 4; sl++) {
                int row = rbase + ((sl >> 1) * 16) + ((sl & 1) * 8);
                if (row < Nn) {
                    g_as[row * NHEAD + head] = asv[sl];
                    g_ad[row * NHEAD + head] = adv[sl];
                }
            }
        }
    }
}

// ------- SINGLE-PASS agg: unnormalized exp-weighted gather, divide at end ----
__device__ __forceinline__ float lrelu(float e) {
    return e > 0.f ? e : NEG_SLOPE * e;
}

__global__ void __launch_bounds__(256) agg_kernel(const float* __restrict__ bias,
                                                  const float* __restrict__ gamma,
                                                  const float* __restrict__ beta,
                                                  float* __restrict__ out) {
    int wid = threadIdx.x >> 5, lane = threadIdx.x & 31;
    int n = blockIdx.x * 8 + wid;
    if (n >= Nn) return;
    int start = g_off[n], end = g_off[n + 1];
    int head = lane >> 3;                     // lane owns 8 contiguous channels
    float adh = g_ad[n * NHEAD + head];

    float acc[8] = {0.f, 0.f, 0.f, 0.f, 0.f, 0.f, 0.f, 0.f};
    float sw = 0.f;
    int e = start;
    for (; e + 4 <= end; e += 4) {            // unroll x4: 4 independent chains
        int s0 = g_csr[e + 0];
        int s1 = g_csr[e + 1];
        int s2 = g_csr[e + 2];
        int s3 = g_csr[e + 3];
        float w0 = __expf(lrelu(g_as[s0 * NHEAD + head] + adh));
        float w1 = __expf(lrelu(g_as[s1 * NHEAD + head] + adh));
        float w2 = __expf(lrelu(g_as[s2 * NHEAD + head] + adh));
        float w3 = __expf(lrelu(g_as[s3 * NHEAD + head] + adh));
        uint4 hv0 = *((const uint4*)(g_h + (size_t)s0 * HCn) + lane);
        uint4 hv1 = *((const uint4*)(g_h + (size_t)s1 * HCn) + lane);
        uint4 hv2 = *((const uint4*)(g_h + (size_t)s2 * HCn) + lane);
        uint4 hv3 = *((const uint4*)(g_h + (size_t)s3 * HCn) + lane);
        sw += (w0 + w1) + (w2 + w3);
        const __half2* a2 = (const __half2*)&hv0;
        const __half2* b2 = (const __half2*)&hv1;
        const __half2* c2 = (const __half2*)&hv2;
        const __half2* d2 = (const __half2*)&hv3;
        #pragma unroll
        for (int j = 0; j < 4; j++) {
            float2 fa = __half22float2(a2[j]);
            float2 fb = __half22float2(b2[j]);
            float2 fc = __half22float2(c2[j]);
            float2 fd = __half22float2(d2[j]);
            acc[j * 2]     += fa.x * w0 + fb.x * w1 + fc.x * w2 + fd.x * w3;
            acc[j * 2 + 1] += fa.y * w0 + fb.y * w1 + fc.y * w2 + fd.y * w3;
        }
    }
    for (; e < end; e++) {
        int s0 = g_csr[e];
        float w0 = __expf(lrelu(g_as[s0 * NHEAD + head] + adh));
        uint4 hv0 = *((const uint4*)(g_h + (size_t)s0 * HCn) + lane);
        sw += w0;
        const __half2* a2 = (const __half2*)&hv0;
        #pragma unroll
        for (int j = 0; j < 4; j++) {
            float2 fa = __half22float2(a2[j]);
            acc[j * 2]     += fa.x * w0;
            acc[j * 2 + 1] += fa.y * w0;
        }
    }

    float inv = 1.f / sw;

    float4 b0 = *(const float4*)(bias + lane * 8);
    float4 b1 = *(const float4*)(bias + lane * 8 + 4);
    float bb[8] = {b0.x, b0.y, b0.z, b0.w, b1.x, b1.y, b1.z, b1.w};
    #pragma unroll
    for (int j = 0; j < 8; j++) acc[j] = acc[j] * inv + bb[j];

    float s1 = 0.f, s2 = 0.f;
    #pragma unroll
    for (int j = 0; j < 8; j++) { s1 += acc[j]; s2 += acc[j] * acc[j]; }
    #pragma unroll
    for (int o = 16; o; o >>= 1) {
        s1 += __shfl_xor_sync(0xffffffffu, s1, o);
        s2 += __shfl_xor_sync(0xffffffffu, s2, o);
    }
    float mu = s1 * (1.f / HCn);
    float var = s2 * (1.f / HCn) - mu * mu;
    float rstd = rsqrtf(var + 1e-5f);

    float4 g0 = *(const float4*)(gamma + lane * 8);
    float4 g1 = *(const float4*)(gamma + lane * 8 + 4);
    float4 t0 = *(const float4*)(beta + lane * 8);
    float4 t1 = *(const float4*)(beta + lane * 8 + 4);
    float gm[8] = {g0.x, g0.y, g0.z, g0.w, g1.x, g1.y, g1.z, g1.w};
    float bt[8] = {t0.x, t0.y, t0.z, t0.w, t1.x, t1.y, t1.z, t1.w};

    float o8[8];
    #pragma unroll
    for (int j = 0; j < 8; j++) {
        float nm = (acc[j] - mu) * rstd * gm[j] + bt[j];
        o8[j] = nm > 0.f ? nm : expm1f(nm);
    }
    float* op = out + (size_t)n * HCn + lane * 8;
    *(float4*)op       = make_float4(o8[0], o8[1], o8[2], o8[3]);
    *(float4*)(op + 4) = make_float4(o8[4], o8[5], o8[6], o8[7]);
}

// ---------------- launch ------------------------------------------------------
extern "C" void kernel_launch(void* const* d_in, const int* in_sizes, int n_in,
                              void* d_out, int out_size) {
    const float* x       = (const float*)d_in[0];
    const void*  ei      = d_in[1];
    const float* W       = (const float*)d_in[2];
    const float* att_src = (const float*)d_in[3];
    const float* att_dst = (const float*)d_in[4];
    const float* bias    = (const float*)d_in[5];
    const float* gamma   = (const float*)d_in[6];
    const float* beta    = (const float*)d_in[7];
    float* out = (float*)d_out;

    static cudaStream_t sB = nullptr;
    static cudaEvent_t eFork = nullptr, eJoin = nullptr;
    static bool streams_ok = false;
    if (!sB) {
        streams_ok =
            (cudaStreamCreateWithFlags(&sB, cudaStreamNonBlocking) == cudaSuccess) &&
            (cudaEventCreateWithFlags(&eFork, cudaEventDisableTiming) == cudaSuccess) &&
            (cudaEventCreateWithFlags(&eJoin, cudaEventDisableTiming) == cudaSuccess);
    }
    cudaFuncSetAttribute(gemm_mma_kernel, cudaFuncAttributeMaxDynamicSharedMemorySize,
                         GEMM_SMEM);

    detect_kernel<<<1, 32>>>((const long long*)ei);

    cudaStream_t csr = streams_ok ? sB : (cudaStream_t)0;
    if (streams_ok) {
        cudaEventRecord(eFork, 0);
        cudaStreamWaitEvent(sB, eFork, 0);
    }

    // CSR-build chain on side stream (R11 structure + merged spine/apply)
    init_count_kernel<<<(Nn + 255) / 256, 256, 0, csr>>>();
    convert_count_kernel<<<(Ee + 255) / 256, 256, 0, csr>>>(ei);
    scan_block_kernel<<<NSB, SB, 0, csr>>>();
    scan_apply_kernel<<<NSB, SB, 0, csr>>>();
    fill_kernel<<<(Ee + 255) / 256, 256, 0, csr>>>();
    if (streams_ok) cudaEventRecord(eJoin, sB);

    // GEMM on main stream
    gemm_mma_kernel<<<dim3(2, (Nn + 127) / 128), 256, GEMM_SMEM>>>(x, W, att_src, att_dst);

    if (streams_ok) cudaStreamWaitEvent((cudaStream_t)0, eJoin, 0);
    agg_kernel<<<(Nn + 7) / 8, 256>>>(bias, gamma, beta, out);
}

// round 15
// speedup vs baseline: 1.0437x; 1.0006x over previous
#include <cuda_runtime.h>
#include <cuda_fp16.h>
#include <math.h>
#include <stdint.h>

#define Nn 50000
#define Ee 800000
#define KIN 128
#define HCn 256
#define NHEAD 4
#define OC 64
#define NEG_SLOPE 0.2f

// ---------------- scratch (static device globals; no allocation) -------------
__device__ __align__(16) __half g_h[(size_t)Nn * HCn];   // 25.6 MB, fp16 features
__device__ float g_as[Nn * NHEAD];
__device__ float g_ad[Nn * NHEAD];
__device__ int   g_src[Ee];
__device__ int   g_dst[Ee];
__device__ int   g_count[Nn];
__device__ int   g_cursor[Nn];
__device__ int   g_off[Nn + 1];
__device__ int   g_csr[Ee + Nn];
__device__ int   g_is64;

#define SB 1024
#define NSB ((Nn + SB - 1) / SB)            // 49
__device__ int   g_bsum[NSB];

__device__ __forceinline__ uint32_t smem_to_u32(const void* smem_ptr) {
    uint32_t addr;
    asm("{ .reg .u64 tmp; cvta.to.shared.u64 tmp, %1; cvt.u32.u64 %0, tmp; }"
        : "=r"(addr) : "l"(smem_ptr));
    return addr;
}

// ---------------- edge index dtype detection ---------------------------------
__global__ void detect_kernel(const long long* __restrict__ ei) {
    if (threadIdx.x == 0) {
        int ok = 1;
        for (int i = 0; i < 8; i++) {
            long long v = ei[i];
            if (v < 0 || v >= Nn) ok = 0;
        }
        g_is64 = ok;
    }
}

__global__ void init_count_kernel() {
    int i = blockIdx.x * blockDim.x + threadIdx.x;
    if (i < Nn) g_count[i] = 1;             // self loop pre-counted
}

// convert + histogram in ONE pass over the edge list (staged int32 src/dst)
__global__ void convert_count_kernel(const void* __restrict__ ei) {
    int i = blockIdx.x * blockDim.x + threadIdx.x;
    if (i >= Ee) return;
    int s, d;
    if (g_is64) {
        const long long* p = (const long long*)ei;
        s = (int)p[i];
        d = (int)p[Ee + i];
    } else {
        const int* p = (const int*)ei;
        s = p[i];
        d = p[Ee + i];
    }
    g_src[i] = s;
    g_dst[i] = d;
    atomicAdd(&g_count[d], 1);
}

// ---------------- scan phase 1: per-block local exclusive scan ---------------
__global__ void __launch_bounds__(SB) scan_block_kernel() {
    __shared__ int sh[SB];
    int i = blockIdx.x * SB + threadIdx.x;
    int v = (i < Nn) ? g_count[i] : 0;
    sh[threadIdx.x] = v;
    __syncthreads();
    #pragma unroll
    for (int o = 1; o < SB; o <<= 1) {
        int t = (threadIdx.x >= o) ? sh[threadIdx.x - o] : 0;
        __syncthreads();
        sh[threadIdx.x] += t;
        __syncthreads();
    }
    if (i < Nn) g_off[i] = sh[threadIdx.x] - v;          // local exclusive
    if (threadIdx.x == SB - 1) g_bsum[blockIdx.x] = sh[SB - 1];
}

// ---------------- scan phase 2 (merged spine+apply) ---------------------------
// Each block redundantly computes the 49-element spine prefix (cheap), then
// applies it. Also writes the self-loop entry directly (slot off[n]) and
// starts cursors at off[n]+1, so fill needs NO self-loop atomics.
__global__ void __launch_bounds__(SB) scan_apply_kernel() {
    __shared__ int pre_sh;
    __shared__ int tot_sh;
    if (threadIdx.x == 0) {
        int pre = 0, tot = 0;
        #pragma unroll
        for (int b = 0; b < NSB; b++) {
            int v = g_bsum[b];
            if (b < (int)blockIdx.x) pre += v;
            tot += v;
        }
        pre_sh = pre;
        tot_sh = tot;
    }
    __syncthreads();
    int i = blockIdx.x * SB + threadIdx.x;
    if (i < Nn) {
        int o = g_off[i] + pre_sh;
        g_off[i] = o;
        g_cursor[i] = o + 1;                 // slot o reserved for self loop
        g_csr[o] = i;                        // self loop
    }
    if (blockIdx.x == NSB - 1 && threadIdx.x == SB - 1) g_off[Nn] = tot_sh;
}

__global__ void fill_kernel() {
    int i = blockIdx.x * blockDim.x + threadIdx.x;
    if (i < Ee) {
        int d = g_dst[i];
        int pos = atomicAdd(&g_cursor[d], 1);
        g_csr[pos] = g_src[i];
    }
}

// ================= GEMM: h = x @ W via HMMA, single-term fp16 ================
#define ASTR 272                    // 128 fp16 = 256B + 16B pad (cf ldmatrix)
#define GS_A 0
#define GS_B (128 * ASTR)           // 34816
#define GEMM_SMEM (2 * 128 * ASTR)  // 69632 B -> 2 CTA/SM

__device__ __forceinline__ void ldmx4(uint32_t* r, uint32_t addr) {
    asm volatile("ldmatrix.sync.aligned.m8n8.x4.shared.b16 {%0,%1,%2,%3}, [%4];"
                 : "=r"(r[0]), "=r"(r[1]), "=r"(r[2]), "=r"(r[3]) : "r"(addr));
}
__device__ __forceinline__ void ldmx4t(uint32_t& r0, uint32_t& r1, uint32_t& r2,
                                       uint32_t& r3, uint32_t addr) {
    asm volatile("ldmatrix.sync.aligned.m8n8.x4.trans.shared.b16 {%0,%1,%2,%3}, [%4];"
                 : "=r"(r0), "=r"(r1), "=r"(r2), "=r"(r3) : "r"(addr));
}
__device__ __forceinline__ void mma16816(float* c, const uint32_t* a, const uint32_t* b) {
    asm volatile("mma.sync.aligned.m16n8k16.row.col.f32.f16.f16.f32 "
                 "{%0,%1,%2,%3}, {%4,%5,%6,%7}, {%8,%9}, {%0,%1,%2,%3};"
                 : "+f"(c[0]), "+f"(c[1]), "+f"(c[2]), "+f"(c[3])
                 : "r"(a[0]), "r"(a[1]), "r"(a[2]), "r"(a[3]), "r"(b[0]), "r"(b[1]));
}

__device__ __forceinline__ uint32_t pack_h2(float a, float b) {
    __half2 h = __floats2half2_rn(a, b);
    return *(uint32_t*)&h;
}

__global__ void __launch_bounds__(256, 2) gemm_mma_kernel(const float* __restrict__ x,
                                                          const float* __restrict__ W,
                                                          const float* __restrict__ att_src,
                                                          const float* __restrict__ att_dst) {
    extern __shared__ char smem[];
    uint32_t sb = smem_to_u32(smem);
    int tid = threadIdx.x, wid = tid >> 5, lane = tid & 31;
    int m_blk = blockIdx.y * 128;
    int n_blk = blockIdx.x * 128;

    #pragma unroll
    for (int i = 0; i < 16; i++) {
        int idx = tid + i * 256;
        int r = idx >> 5;
        int kq = (idx & 31) * 4;
        int grow = m_blk + r;
        float4 v = (grow < Nn) ? *(const float4*)(x + (size_t)grow * KIN + kq)
                               : make_float4(0.f, 0.f, 0.f, 0.f);
        *(uint2*)(smem + GS_A + (uint32_t)r * ASTR + kq * 2) =
            make_uint2(pack_h2(v.x, v.y), pack_h2(v.z, v.w));
    }
    #pragma unroll
    for (int i = 0; i < 16; i++) {
        int idx = tid + i * 256;
        int k = idx >> 5;
        int nq = (idx & 31) * 4;
        float4 v = *(const float4*)(W + (size_t)k * HCn + n_blk + nq);
        *(uint2*)(smem + GS_B + (uint32_t)k * ASTR + nq * 2) =
            make_uint2(pack_h2(v.x, v.y), pack_h2(v.z, v.w));
    }
    __syncthreads();

    int m0 = (wid & 3) * 32;
    int n0 = (wid >> 2) * 64;
    float c[2][8][4] = {};

    int a_r16 = (lane & 7) + ((lane >> 3) & 1) * 8;
    int a_k8  = (lane >> 4) * 8;
    int b_mi  = lane >> 3;
    int b_k8  = (lane & 7) + (b_mi & 1) * 8;
    int b_n8  = (b_mi >> 1) * 8;

    #pragma unroll
    for (int k0 = 0; k0 < KIN; k0 += 16) {
        uint32_t a[2][4];
        #pragma unroll
        for (int mt = 0; mt < 2; mt++) {
            uint32_t addr = sb + GS_A + (uint32_t)(m0 + mt * 16 + a_r16) * ASTR
                          + (uint32_t)(k0 + a_k8) * 2;
            ldmx4(a[mt], addr);
        }
        uint32_t b[8][2];
        #pragma unroll
        for (int q = 0; q < 4; q++) {
            uint32_t addr = sb + GS_B + (uint32_t)(k0 + b_k8) * ASTR
                          + (uint32_t)(n0 + q * 16 + b_n8) * 2;
            uint32_t r0, r1, r2, r3;
            ldmx4t(r0, r1, r2, r3, addr);
            b[q * 2][0] = r0;     b[q * 2][1] = r1;
            b[q * 2 + 1][0] = r2; b[q * 2 + 1][1] = r3;
        }
        #pragma unroll
        for (int mt = 0; mt < 2; mt++)
            #pragma unroll
            for (int nt = 0; nt < 8; nt++)
                mma16816(c[mt][nt], a[mt], b[nt]);
    }

    // epilogue 1: store h as fp16
    int gr0 = m_blk + m0 + (lane >> 2);
    int gc0 = n_blk + n0 + (lane & 3) * 2;
    #pragma unroll
    for (int mt = 0; mt < 2; mt++) {
        #pragma unroll
        for (int nt = 0; nt < 8; nt++) {
            int row = gr0 + mt * 16;
            int col = gc0 + nt * 8;
            if (row < Nn)
                *(__half2*)(g_h + (size_t)row * HCn + col) =
                    __floats2half2_rn(c[mt][nt][0], c[mt][nt][1]);
            if (row + 8 < Nn)
                *(__half2*)(g_h + (size_t)(row + 8) * HCn + col) =
                    __floats2half2_rn(c[mt][nt][2], c[mt][nt][3]);
        }
    }

    // epilogue 2: fused attention halves. This warp's 64 cols == one head.
    {
        int head = (n_blk + n0) >> 6;
        const float* ws = att_src + head * OC;
        const float* wd = att_dst + head * OC;
        float asv[4] = {0.f, 0.f, 0.f, 0.f};
        float adv[4] = {0.f, 0.f, 0.f, 0.f};
        int cbase = (lane & 3) * 2;
        #pragma unroll
        for (int nt = 0; nt < 8; nt++) {
            float2 s2 = *(const float2*)(ws + nt * 8 + cbase);
            float2 d2 = *(const float2*)(wd + nt * 8 + cbase);
            #pragma unroll
            for (int sl = 0; sl < 4; sl++) {
                float c0 = c[sl >> 1][nt][(sl & 1) * 2];
                float c1 = c[sl >> 1][nt][(sl & 1) * 2 + 1];
                asv[sl] += c0 * s2.x + c1 * s2.y;
                adv[sl] += c0 * d2.x + c1 * d2.y;
            }
        }
        #pragma unroll
        for (int o = 1; o < 4; o <<= 1) {
            #pragma unroll
            for (int sl = 0; sl < 4; sl++) {
                asv[sl] += __shfl_xor_sync(0xffffffffu, asv[sl], o);
                adv[sl] += __shfl_xor_sync(0xffffffffu, adv[sl], o);
            }
        }
        if ((lane & 3) == 0) {
            int rbase = m_blk + m0 + (lane >> 2);
            #pragma unroll
            for (int sl = 0; sl < 4; sl++) {
                int row = rbase + ((sl >> 1) * 16) + ((sl & 1) * 8);
                if (row < Nn) {
                    g_as[row * NHEAD + head] = asv[sl];
                    g_ad[row * NHEAD + head] = adv[sl];
                }
            }
        }
    }
}

// ------- SINGLE-PASS agg: unnormalized exp-weighted gather, divide at end ----
__device__ __forceinline__ float lrelu(float e) {
    return e > 0.f ? e : NEG_SLOPE * e;
}

__global__ void __launch_bounds__(256) agg_kernel(const float* __restrict__ bias,
                                                  const float* __restrict__ gamma,
                                                  const float* __restrict__ beta,
                                                  float* __restrict__ out) {
    int wid = threadIdx.x >> 5, lane = threadIdx.x & 31;
    int n = blockIdx.x * 8 + wid;
    if (n >= Nn) return;
    int start = g_off[n], end = g_off[n + 1];
    int head = lane >> 3;                     // lane owns 8 contiguous channels
    float adh = g_ad[n * NHEAD + head];

    float acc[8] = {0.f, 0.f, 0.f, 0.f, 0.f, 0.f, 0.f, 0.f};
    float sw = 0.f;
    int e = start;
    for (; e + 4 <= end; e += 4) {            // unroll x4: 4 independent chains
        int s0 = g_csr[e + 0];
        int s1 = g_csr[e + 1];
        int s2 = g_csr[e + 2];
        int s3 = g_csr[e + 3];
        float w0 = __expf(lrelu(g_as[s0 * NHEAD + head] + adh));
        float w1 = __expf(lrelu(g_as[s1 * NHEAD + head] + adh));
        float w2 = __expf(lrelu(g_as[s2 * NHEAD + head] + adh));
        float w3 = __expf(lrelu(g_as[s3 * NHEAD + head] + adh));
        uint4 hv0 = *((const uint4*)(g_h + (size_t)s0 * HCn) + lane);
        uint4 hv1 = *((const uint4*)(g_h + (size_t)s1 * HCn) + lane);
        uint4 hv2 = *((const uint4*)(g_h + (size_t)s2 * HCn) + lane);
        uint4 hv3 = *((const uint4*)(g_h + (size_t)s3 * HCn) + lane);
        sw += (w0 + w1) + (w2 + w3);
        const __half2* a2 = (const __half2*)&hv0;
        const __half2* b2 = (const __half2*)&hv1;
        const __half2* c2 = (const __half2*)&hv2;
        const __half2* d2 = (const __half2*)&hv3;
        #pragma unroll
        for (int j = 0; j < 4; j++) {
            float2 fa = __half22float2(a2[j]);
            float2 fb = __half22float2(b2[j]);
            float2 fc = __half22float2(c2[j]);
            float2 fd = __half22float2(d2[j]);
            acc[j * 2]     += fa.x * w0 + fb.x * w1 + fc.x * w2 + fd.x * w3;
            acc[j * 2 + 1] += fa.y * w0 + fb.y * w1 + fc.y * w2 + fd.y * w3;
        }
    }
    for (; e < end; e++) {
        int s0 = g_csr[e];
        float w0 = __expf(lrelu(g_as[s0 * NHEAD + head] + adh));
        uint4 hv0 = *((const uint4*)(g_h + (size_t)s0 * HCn) + lane);
        sw += w0;
        const __half2* a2 = (const __half2*)&hv0;
        #pragma unroll
        for (int j = 0; j < 4; j++) {
            float2 fa = __half22float2(a2[j]);
            acc[j * 2]     += fa.x * w0;
            acc[j * 2 + 1] += fa.y * w0;
        }
    }

    float inv = 1.f / sw;

    float4 b0 = *(const float4*)(bias + lane * 8);
    float4 b1 = *(const float4*)(bias + lane * 8 + 4);
    float bb[8] = {b0.x, b0.y, b0.z, b0.w, b1.x, b1.y, b1.z, b1.w};
    #pragma unroll
    for (int j = 0; j < 8; j++) acc[j] = acc[j] * inv + bb[j];

    float s1 = 0.f, s2 = 0.f;
    #pragma unroll
    for (int j = 0; j < 8; j++) { s1 += acc[j]; s2 += acc[j] * acc[j]; }
    #pragma unroll
    for (int o = 16; o; o >>= 1) {
        s1 += __shfl_xor_sync(0xffffffffu, s1, o);
        s2 += __shfl_xor_sync(0xffffffffu, s2, o);
    }
    float mu = s1 * (1.f / HCn);
    float var = s2 * (1.f / HCn) - mu * mu;
    float rstd = rsqrtf(var + 1e-5f);

    float4 g0 = *(const float4*)(gamma + lane * 8);
    float4 g1 = *(const float4*)(gamma + lane * 8 + 4);
    float4 t0 = *(const float4*)(beta + lane * 8);
    float4 t1 = *(const float4*)(beta + lane * 8 + 4);
    float gm[8] = {g0.x, g0.y, g0.z, g0.w, g1.x, g1.y, g1.z, g1.w};
    float bt[8] = {t0.x, t0.y, t0.z, t0.w, t1.x, t1.y, t1.z, t1.w};

    float o8[8];
    #pragma unroll
    for (int j = 0; j < 8; j++) {
        float nm = (acc[j] - mu) * rstd * gm[j] + bt[j];
        o8[j] = nm > 0.f ? nm : expm1f(nm);
    }
    float* op = out + (size_t)n * HCn + lane * 8;
    *(float4*)op       = make_float4(o8[0], o8[1], o8[2], o8[3]);
    *(float4*)(op + 4) = make_float4(o8[4], o8[5], o8[6], o8[7]);
}

// ---------------- launch ------------------------------------------------------
extern "C" void kernel_launch(void* const* d_in, const int* in_sizes, int n_in,
                              void* d_out, int out_size) {
    const float* x       = (const float*)d_in[0];
    const void*  ei      = d_in[1];
    const float* W       = (const float*)d_in[2];
    const float* att_src = (const float*)d_in[3];
    const float* att_dst = (const float*)d_in[4];
    const float* bias    = (const float*)d_in[5];
    const float* gamma   = (const float*)d_in[6];
    const float* beta    = (const float*)d_in[7];
    float* out = (float*)d_out;

    static cudaStream_t sB = nullptr;
    static cudaEvent_t eFork = nullptr, eJoin = nullptr;
    static bool streams_ok = false;
    if (!sB) {
        streams_ok =
            (cudaStreamCreateWithFlags(&sB, cudaStreamNonBlocking) == cudaSuccess) &&
            (cudaEventCreateWithFlags(&eFork, cudaEventDisableTiming) == cudaSuccess) &&
            (cudaEventCreateWithFlags(&eJoin, cudaEventDisableTiming) == cudaSuccess);
    }
    cudaFuncSetAttribute(gemm_mma_kernel, cudaFuncAttributeMaxDynamicSharedMemorySize,
                         GEMM_SMEM);

    detect_kernel<<<1, 32>>>((const long long*)ei);

    cudaStream_t csr = streams_ok ? sB : (cudaStream_t)0;
    if (streams_ok) {
        cudaEventRecord(eFork, 0);
        cudaStreamWaitEvent(sB, eFork, 0);
    }

    // CSR-build chain on side stream (R11 structure + merged spine/apply)
    init_count_kernel<<<(Nn + 255) / 256, 256, 0, csr>>>();
    convert_count_kernel<<<(Ee + 255) / 256, 256, 0, csr>>>(ei);
    scan_block_kernel<<<NSB, SB, 0, csr>>>();
    scan_apply_kernel<<<NSB, SB, 0, csr>>>();
    fill_kernel<<<(Ee + 255) / 256, 256, 0, csr>>>();
    if (streams_ok) cudaEventRecord(eJoin, sB);

    // GEMM on main stream
    gemm_mma_kernel<<<dim3(2, (Nn + 127) / 128), 256, GEMM_SMEM>>>(x, W, att_src, att_dst);

    if (streams_ok) cudaStreamWaitEvent((cudaStream_t)0, eJoin, 0);
    agg_kernel<<<(Nn + 7) / 8, 256>>>(bias, gamma, beta, out);
}

// round 16
// speedup vs baseline: 1.0493x; 1.0053x over previous
#include <cuda_runtime.h>
#include <cuda_fp16.h>
#include <math.h>
#include <stdint.h>

#define Nn 50000
#define Ee 800000
#define EHALF (Ee / 2)
#define KIN 128
#define HCn 256
#define NHEAD 4
#define OC 64
#define NEG_SLOPE 0.2f

// ---------------- scratch (static device globals; no allocation) -------------
// g_count relies on zero-initialization of __device__ globals; scan_apply
// re-zeroes it each call so every invocation sees identical state.
__device__ __align__(16) __half g_h[(size_t)Nn * HCn];   // 25.6 MB, fp16 features
__device__ float g_as[Nn * NHEAD];
__device__ float g_ad[Nn * NHEAD];
__device__ int   g_src[Ee];
__device__ int   g_dst[Ee];
__device__ int   g_count[Nn];
__device__ int   g_cursor[Nn];
__device__ int   g_off[Nn + 1];
__device__ int   g_csr[Ee + Nn];

#define SB 1024
#define NSB ((Nn + SB - 1) / SB)            // 49
__device__ int   g_bsum[NSB];

__device__ __forceinline__ uint32_t smem_to_u32(const void* smem_ptr) {
    uint32_t addr;
    asm("{ .reg .u64 tmp; cvta.to.shared.u64 tmp, %1; cvt.u32.u64 %0, tmp; }"
        : "=r"(addr) : "l"(smem_ptr));
    return addr;
}

// ---- convert + histogram in ONE pass; per-block dtype detection -------------
__global__ void convert_count_kernel(const void* __restrict__ ei) {
    __shared__ int s64;
    if (threadIdx.x == 0) {
        const long long* p = (const long long*)ei;
        int ok = 1;
        #pragma unroll
        for (int j = 0; j < 8; j++) {
            long long v = p[j];
            if (v < 0 || v >= Nn) ok = 0;   // int32 pairs read as int64 blow past Nn
        }
        s64 = ok;
    }
    __syncthreads();
    int i = blockIdx.x * blockDim.x + threadIdx.x;
    if (i >= Ee) return;
    int s, d;
    if (s64) {
        const long long* p = (const long long*)ei;
        s = (int)p[i];
        d = (int)p[Ee + i];
    } else {
        const int* p = (const int*)ei;
        s = p[i];
        d = p[Ee + i];
    }
    g_src[i] = s;
    g_dst[i] = d;
    atomicAdd(&g_count[d], 1);
}

// ---------------- scan phase 1: per-block local exclusive scan ---------------
// +1 per node accounts for the self loop (g_count holds only real edges).
__global__ void __launch_bounds__(SB) scan_block_kernel() {
    __shared__ int sh[SB];
    int i = blockIdx.x * SB + threadIdx.x;
    int v = (i < Nn) ? g_count[i] + 1 : 0;
    sh[threadIdx.x] = v;
    __syncthreads();
    #pragma unroll
    for (int o = 1; o < SB; o <<= 1) {
        int t = (threadIdx.x >= o) ? sh[threadIdx.x - o] : 0;
        __syncthreads();
        sh[threadIdx.x] += t;
        __syncthreads();
    }
    if (i < Nn) g_off[i] = sh[threadIdx.x] - v;          // local exclusive
    if (threadIdx.x == SB - 1) g_bsum[blockIdx.x] = sh[SB - 1];
}

// ---------------- scan phase 2 (merged spine+apply) ---------------------------
// Redundant 49-element spine per block; writes self-loop slot directly; zeroes
// g_count for the next invocation (keeps every call deterministic).
__global__ void __launch_bounds__(SB) scan_apply_kernel() {
    __shared__ int pre_sh;
    __shared__ int tot_sh;
    if (threadIdx.x == 0) {
        int pre = 0, tot = 0;
        #pragma unroll
        for (int b = 0; b < NSB; b++) {
            int v = g_bsum[b];
            if (b < (int)blockIdx.x) pre += v;
            tot += v;
        }
        pre_sh = pre;
        tot_sh = tot;
    }
    __syncthreads();
    int i = blockIdx.x * SB + threadIdx.x;
    if (i < Nn) {
        int o = g_off[i] + pre_sh;
        g_off[i] = o;
        g_cursor[i] = o + 1;                 // slot o reserved for self loop
        g_csr[o] = i;                        // self loop
        g_count[i] = 0;                      // reset for next call
    }
    if (blockIdx.x == NSB - 1 && threadIdx.x == SB - 1) g_off[Nn] = tot_sh;
}

// fill over an edge range [lo, hi) — split across two streams
__global__ void fill_kernel(int lo, int hi) {
    int i = lo + blockIdx.x * blockDim.x + threadIdx.x;
    if (i < hi) {
        int d = g_dst[i];
        int pos = atomicAdd(&g_cursor[d], 1);
        g_csr[pos] = g_src[i];
    }
}

// ================= GEMM: h = x @ W via HMMA, single-term fp16 ================
#define ASTR 272                    // 128 fp16 = 256B + 16B pad (cf ldmatrix)
#define GS_A 0
#define GS_B (128 * ASTR)           // 34816
#define GEMM_SMEM (2 * 128 * ASTR)  // 69632 B -> 2 CTA/SM

__device__ __forceinline__ void ldmx4(uint32_t* r, uint32_t addr) {
    asm volatile("ldmatrix.sync.aligned.m8n8.x4.shared.b16 {%0,%1,%2,%3}, [%4];"
                 : "=r"(r[0]), "=r"(r[1]), "=r"(r[2]), "=r"(r[3]) : "r"(addr));
}
__device__ __forceinline__ void ldmx4t(uint32_t& r0, uint32_t& r1, uint32_t& r2,
                                       uint32_t& r3, uint32_t addr) {
    asm volatile("ldmatrix.sync.aligned.m8n8.x4.trans.shared.b16 {%0,%1,%2,%3}, [%4];"
                 : "=r"(r0), "=r"(r1), "=r"(r2), "=r"(r3) : "r"(addr));
}
__device__ __forceinline__ void mma16816(float* c, const uint32_t* a, const uint32_t* b) {
    asm volatile("mma.sync.aligned.m16n8k16.row.col.f32.f16.f16.f32 "
                 "{%0,%1,%2,%3}, {%4,%5,%6,%7}, {%8,%9}, {%0,%1,%2,%3};"
                 : "+f"(c[0]), "+f"(c[1]), "+f"(c[2]), "+f"(c[3])
                 : "r"(a[0]), "r"(a[1]), "r"(a[2]), "r"(a[3]), "r"(b[0]), "r"(b[1]));
}

__device__ __forceinline__ uint32_t pack_h2(float a, float b) {
    __half2 h = __floats2half2_rn(a, b);
    return *(uint32_t*)&h;
}

__global__ void __launch_bounds__(256, 2) gemm_mma_kernel(const float* __restrict__ x,
                                                          const float* __restrict__ W,
                                                          const float* __restrict__ att_src,
                                                          const float* __restrict__ att_dst) {
    extern __shared__ char smem[];
    uint32_t sb = smem_to_u32(smem);
    int tid = threadIdx.x, wid = tid >> 5, lane = tid & 31;
    int m_blk = blockIdx.y * 128;
    int n_blk = blockIdx.x * 128;

    #pragma unroll
    for (int i = 0; i < 16; i++) {
        int idx = tid + i * 256;
        int r = idx >> 5;
        int kq = (idx & 31) * 4;
        int grow = m_blk + r;
        float4 v = (grow < Nn) ? *(const float4*)(x + (size_t)grow * KIN + kq)
                               : make_float4(0.f, 0.f, 0.f, 0.f);
        *(uint2*)(smem + GS_A + (uint32_t)r * ASTR + kq * 2) =
            make_uint2(pack_h2(v.x, v.y), pack_h2(v.z, v.w));
    }
    #pragma unroll
    for (int i = 0; i < 16; i++) {
        int idx = tid + i * 256;
        int k = idx >> 5;
        int nq = (idx & 31) * 4;
        float4 v = *(const float4*)(W + (size_t)k * HCn + n_blk + nq);
        *(uint2*)(smem + GS_B + (uint32_t)k * ASTR + nq * 2) =
            make_uint2(pack_h2(v.x, v.y), pack_h2(v.z, v.w));
    }
    __syncthreads();

    int m0 = (wid & 3) * 32;
    int n0 = (wid >> 2) * 64;
    float c[2][8][4] = {};

    int a_r16 = (lane & 7) + ((lane >> 3) & 1) * 8;
    int a_k8  = (lane >> 4) * 8;
    int b_mi  = lane >> 3;
    int b_k8  = (lane & 7) + (b_mi & 1) * 8;
    int b_n8  = (b_mi >> 1) * 8;

    #pragma unroll
    for (int k0 = 0; k0 < KIN; k0 += 16) {
        uint32_t a[2][4];
        #pragma unroll
        for (int mt = 0; mt < 2; mt++) {
            uint32_t addr = sb + GS_A + (uint32_t)(m0 + mt * 16 + a_r16) * ASTR
                          + (uint32_t)(k0 + a_k8) * 2;
            ldmx4(a[mt], addr);
        }
        uint32_t b[8][2];
        #pragma unroll
        for (int q = 0; q < 4; q++) {
            uint32_t addr = sb + GS_B + (uint32_t)(k0 + b_k8) * ASTR
                          + (uint32_t)(n0 + q * 16 + b_n8) * 2;
            uint32_t r0, r1, r2, r3;
            ldmx4t(r0, r1, r2, r3, addr);
            b[q * 2][0] = r0;     b[q * 2][1] = r1;
            b[q * 2 + 1][0] = r2; b[q * 2 + 1][1] = r3;
        }
        #pragma unroll
        for (int mt = 0; mt < 2; mt++)
            #pragma unroll
            for (int nt = 0; nt < 8; nt++)
                mma16816(c[mt][nt], a[mt], b[nt]);
    }

    // epilogue 1: store h as fp16
    int gr0 = m_blk + m0 + (lane >> 2);
    int gc0 = n_blk + n0 + (lane & 3) * 2;
    #pragma unroll
    for (int mt = 0; mt < 2; mt++) {
        #pragma unroll
        for (int nt = 0; nt < 8; nt++) {
            int row = gr0 + mt * 16;
            int col = gc0 + nt * 8;
            if (row < Nn)
                *(__half2*)(g_h + (size_t)row * HCn + col) =
                    __floats2half2_rn(c[mt][nt][0], c[mt][nt][1]);
            if (row + 8 < Nn)
                *(__half2*)(g_h + (size_t)(row + 8) * HCn + col) =
                    __floats2half2_rn(c[mt][nt][2], c[mt][nt][3]);
        }
    }

    // epilogue 2: fused attention halves. This warp's 64 cols == one head.
    {
        int head = (n_blk + n0) >> 6;
        const float* ws = att_src + head * OC;
        const float* wd = att_dst + head * OC;
        float asv[4] = {0.f, 0.f, 0.f, 0.f};
        float adv[4] = {0.f, 0.f, 0.f, 0.f};
        int cbase = (lane & 3) * 2;
        #pragma unroll
        for (int nt = 0; nt < 8; nt++) {
            float2 s2 = *(const float2*)(ws + nt * 8 + cbase);
            float2 d2 = *(const float2*)(wd + nt * 8 + cbase);
            #pragma unroll
            for (int sl = 0; sl < 4; sl++) {
                float c0 = c[sl >> 1][nt][(sl & 1) * 2];
                float c1 = c[sl >> 1][nt][(sl & 1) * 2 + 1];
                asv[sl] += c0 * s2.x + c1 * s2.y;
                adv[sl] += c0 * d2.x + c1 * d2.y;
            }
        }
        #pragma unroll
        for (int o = 1; o < 4; o <<= 1) {
            #pragma unroll
            for (int sl = 0; sl < 4; sl++) {
                asv[sl] += __shfl_xor_sync(0xffffffffu, asv[sl], o);
                adv[sl] += __shfl_xor_sync(0xffffffffu, adv[sl], o);
            }
        }
        if ((lane & 3) == 0) {
            int rbase = m_blk + m0 + (lane >> 2);
            #pragma unroll
            for (int sl = 0; sl < 4; sl++) {
                int row = rbase + ((sl >> 1) * 16) + ((sl & 1) * 8);
                if (row < Nn) {
                    g_as[row * NHEAD + head] = asv[sl];
                    g_ad[row * NHEAD + head] = adv[sl];
                }
            }
        }
    }
}

// ------- SINGLE-PASS agg: unnormalized exp-weighted gather, divide at end ----
__device__ __forceinline__ float lrelu(float e) {
    return e > 0.f ? e : NEG_SLOPE * e;
}

__global__ void __launch_bounds__(256) agg_kernel(const float* __restrict__ bias,
                                                  const float* __restrict__ gamma,
                                                  const float* __restrict__ beta,
                                                  float* __restrict__ out) {
    int wid = threadIdx.x >> 5, lane = threadIdx.x & 31;
    int n = blockIdx.x * 8 + wid;
    if (n >= Nn) return;
    int start = g_off[n], end = g_off[n + 1];
    int head = lane >> 3;                     // lane owns 8 contiguous channels
    float adh = g_ad[n * NHEAD + head];

    float acc[8] = {0.f, 0.f, 0.f, 0.f, 0.f, 0.f, 0.f, 0.f};
    float sw = 0.f;
    int e = start;
    for (; e + 4 <= end; e += 4) {            // unroll x4: 4 independent chains
        int s0 = g_csr[e + 0];
        int s1 = g_csr[e + 1];
        int s2 = g_csr[e + 2];
        int s3 = g_csr[e + 3];
        float w0 = __expf(lrelu(g_as[s0 * NHEAD + head] + adh));
        float w1 = __expf(lrelu(g_as[s1 * NHEAD + head] + adh));
        float w2 = __expf(lrelu(g_as[s2 * NHEAD + head] + adh));
        float w3 = __expf(lrelu(g_as[s3 * NHEAD + head] + adh));
        uint4 hv0 = *((const uint4*)(g_h + (size_t)s0 * HCn) + lane);
        uint4 hv1 = *((const uint4*)(g_h + (size_t)s1 * HCn) + lane);
        uint4 hv2 = *((const uint4*)(g_h + (size_t)s2 * HCn) + lane);
        uint4 hv3 = *((const uint4*)(g_h + (size_t)s3 * HCn) + lane);
        sw += (w0 + w1) + (w2 + w3);
        const __half2* a2 = (const __half2*)&hv0;
        const __half2* b2 = (const __half2*)&hv1;
        const __half2* c2 = (const __half2*)&hv2;
        const __half2* d2 = (const __half2*)&hv3;
        #pragma unroll
        for (int j = 0; j < 4; j++) {
            float2 fa = __half22float2(a2[j]);
            float2 fb = __half22float2(b2[j]);
            float2 fc = __half22float2(c2[j]);
            float2 fd = __half22float2(d2[j]);
            acc[j * 2]     += fa.x * w0 + fb.x * w1 + fc.x * w2 + fd.x * w3;
            acc[j * 2 + 1] += fa.y * w0 + fb.y * w1 + fc.y * w2 + fd.y * w3;
        }
    }
    for (; e < end; e++) {
        int s0 = g_csr[e];
        float w0 = __expf(lrelu(g_as[s0 * NHEAD + head] + adh));
        uint4 hv0 = *((const uint4*)(g_h + (size_t)s0 * HCn) + lane);
        sw += w0;
        const __half2* a2 = (const __half2*)&hv0;
        #pragma unroll
        for (int j = 0; j < 4; j++) {
            float2 fa = __half22float2(a2[j]);
            acc[j * 2]     += fa.x * w0;
            acc[j * 2 + 1] += fa.y * w0;
        }
    }

    float inv = 1.f / sw;

    float4 b0 = *(const float4*)(bias + lane * 8);
    float4 b1 = *(const float4*)(bias + lane * 8 + 4);
    float bb[8] = {b0.x, b0.y, b0.z, b0.w, b1.x, b1.y, b1.z, b1.w};
    #pragma unroll
    for (int j = 0; j < 8; j++) acc[j] = acc[j] * inv + bb[j];

    float s1 = 0.f, s2 = 0.f;
    #pragma unroll
    for (int j = 0; j < 8; j++) { s1 += acc[j]; s2 += acc[j] * acc[j]; }
    #pragma unroll
    for (int o = 16; o; o >>= 1) {
        s1 += __shfl_xor_sync(0xffffffffu, s1, o);
        s2 += __shfl_xor_sync(0xffffffffu, s2, o);
    }
    float mu = s1 * (1.f / HCn);
    float var = s2 * (1.f / HCn) - mu * mu;
    float rstd = rsqrtf(var + 1e-5f);

    float4 g0 = *(const float4*)(gamma + lane * 8);
    float4 g1 = *(const float4*)(gamma + lane * 8 + 4);
    float4 t0 = *(const float4*)(beta + lane * 8);
    float4 t1 = *(const float4*)(beta + lane * 8 + 4);
    float gm[8] = {g0.x, g0.y, g0.z, g0.w, g1.x, g1.y, g1.z, g1.w};
    float bt[8] = {t0.x, t0.y, t0.z, t0.w, t1.x, t1.y, t1.z, t1.w};

    float o8[8];
    #pragma unroll
    for (int j = 0; j < 8; j++) {
        float nm = (acc[j] - mu) * rstd * gm[j] + bt[j];
        o8[j] = nm > 0.f ? nm : expm1f(nm);
    }
    float* op = out + (size_t)n * HCn + lane * 8;
    *(float4*)op       = make_float4(o8[0], o8[1], o8[2], o8[3]);
    *(float4*)(op + 4) = make_float4(o8[4], o8[5], o8[6], o8[7]);
}

// ---------------- launch ------------------------------------------------------
extern "C" void kernel_launch(void* const* d_in, const int* in_sizes, int n_in,
                              void* d_out, int out_size) {
    const float* x       = (const float*)d_in[0];
    const void*  ei      = d_in[1];
    const float* W       = (const float*)d_in[2];
    const float* att_src = (const float*)d_in[3];
    const float* att_dst = (const float*)d_in[4];
    const float* bias    = (const float*)d_in[5];
    const float* gamma   = (const float*)d_in[6];
    const float* beta    = (const float*)d_in[7];
    float* out = (float*)d_out;

    static cudaStream_t sB = nullptr;
    static cudaEvent_t eFork = nullptr, eScan = nullptr, eJoin = nullptr;
    static bool streams_ok = false;
    if (!sB) {
        streams_ok =
            (cudaStreamCreateWithFlags(&sB, cudaStreamNonBlocking) == cudaSuccess) &&
            (cudaEventCreateWithFlags(&eFork, cudaEventDisableTiming) == cudaSuccess) &&
            (cudaEventCreateWithFlags(&eScan, cudaEventDisableTiming) == cudaSuccess) &&
            (cudaEventCreateWithFlags(&eJoin, cudaEventDisableTiming) == cudaSuccess);
    }
    cudaFuncSetAttribute(gemm_mma_kernel, cudaFuncAttributeMaxDynamicSharedMemorySize,
                         GEMM_SMEM);

    cudaStream_t csr = streams_ok ? sB : (cudaStream_t)0;
    if (streams_ok) {
        cudaEventRecord(eFork, 0);
        cudaStreamWaitEvent(sB, eFork, 0);
    }

    // CSR leg (side stream): convert+count -> scan -> apply -> fill[0, E/2)
    convert_count_kernel<<<(Ee + 255) / 256, 256, 0, csr>>>(ei);
    scan_block_kernel<<<NSB, SB, 0, csr>>>();
    scan_apply_kernel<<<NSB, SB, 0, csr>>>();
    if (streams_ok) cudaEventRecord(eScan, sB);
    fill_kernel<<<(EHALF + 255) / 256, 256, 0, csr>>>(0, EHALF);
    if (streams_ok) cudaEventRecord(eJoin, sB);

    // Main leg: GEMM, then fill[E/2, E) once cursors are ready
    gemm_mma_kernel<<<dim3(2, (Nn + 127) / 128), 256, GEMM_SMEM>>>(x, W, att_src, att_dst);
    if (streams_ok) {
        cudaStreamWaitEvent((cudaStream_t)0, eScan, 0);
        fill_kernel<<<(Ee - EHALF + 255) / 256, 256>>>(EHALF, Ee);
        cudaStreamWaitEvent((cudaStream_t)0, eJoin, 0);
    } else {
        fill_kernel<<<(Ee - EHALF + 255) / 256, 256>>>(EHALF, Ee);
    }
    agg_kernel<<<(Nn + 7) / 8, 256>>>(bias, gamma, beta, out);
}